// round 13
// baseline (speedup 1.0000x reference)
#include <cuda_runtime.h>
#include <math.h>

// ---------------------------------------------------------------------------
// Problem constants (reference: D_MODEL=1024, H=16, DK=DV=64, R=64, C=64,
// KW=4, B=2, T=2048)
// ---------------------------------------------------------------------------
#define DM   1024
#define HH   16
#define DKH  64
#define DVH  64
#define RR   64
#define CC   64
#define KWW  4
#define BB   2
#define TT   2048
#define MR   (BB*TT)        // 4096 rows (b,t)
#define BHN  (BB*HH)        // 32
#define NCH  (TT/CC)        // 32 chunks

// Scratch: 8 big [4096,1024] buffers + hA [4096,64]x2 + beta,g [4096,16]
__device__ float g_scratch[(size_t)8*MR*DM + (size_t)2*MR*RR + (size_t)2*MR*HH];

// ---------------------------------------------------------------------------
// 1. Causal depthwise conv (KW=4) + SiLU, float4-vectorized (4 cols/thread)
// ---------------------------------------------------------------------------
__global__ void conv_silu_kernel(const float* __restrict__ x,
    const float* __restrict__ wq, const float* __restrict__ bq,
    const float* __restrict__ wk, const float* __restrict__ bk,
    const float* __restrict__ wv, const float* __restrict__ bv,
    float* __restrict__ cq, float* __restrict__ ck, float* __restrict__ cv)
{
    int g4 = blockIdx.x*blockDim.x + threadIdx.x;   // float4 group index
    if (g4 >= MR*DM/4) return;
    int base = g4*4;
    int d4  = base & (DM-1);          // column of first element (mult of 4)
    int row = base >> 10;
    int t   = row & (TT-1);

    float4 xs4[KWW];
    #pragma unroll
    for (int j=0;j<KWW;j++){
        int tt2 = t - (KWW-1) + j;
        if (tt2 >= 0) xs4[j] = *(const float4*)(x + base + (j-(KWW-1))*DM);
        else          xs4[j] = make_float4(0.f,0.f,0.f,0.f);
    }
    const float* xsf = (const float*)xs4;   // xsf[j*4+i]

    float4 oq, ok, ov;
    float* oqf = (float*)&oq; float* okf = (float*)&ok; float* ovf = (float*)&ov;
    #pragma unroll
    for (int i=0;i<4;i++){
        int d = d4 + i;
        float yq=bq[d], yk=bk[d], yv=bv[d];
        #pragma unroll
        for (int j=0;j<KWW;j++){
            float xv = xsf[j*4+i];
            yq += xv*wq[d*KWW+j];
            yk += xv*wk[d*KWW+j];
            yv += xv*wv[d*KWW+j];
        }
        oqf[i] = yq / (1.f + __expf(-yq));
        okf[i] = yk / (1.f + __expf(-yk));
        ovf[i] = yv / (1.f + __expf(-yv));
    }
    *(float4*)(cq + base) = oq;
    *(float4*)(ck + base) = ok;
    *(float4*)(cv + base) = ov;
}

// ---------------------------------------------------------------------------
// 2a. TF32 tensor-core GEMM batch: C[M,N] = A[M,K] @ B[N,K]^T + bias[N]
//     128x128 block tile, BK=32, 8 warps (4m x 2n), warp tile 32x64,
//     mma.sync.m16n8k8.tf32. Register prefetch + DOUBLE-BUFFERED smem.
//     blockIdx.z selects (A, W, bias, C) from the by-value pointer batch.
// ---------------------------------------------------------------------------
struct GemmB {
    const float* A[3];
    const float* W[3];
    const float* bias[3];
    float*       C[3];
};

__device__ __forceinline__ unsigned f2tf(float f){
    unsigned u; asm("cvt.rna.tf32.f32 %0, %1;" : "=r"(u) : "f"(f)); return u;
}
__device__ __forceinline__ uint4 f2tf4(float4 f){
    uint4 u; u.x=f2tf(f.x); u.y=f2tf(f.y); u.z=f2tf(f.z); u.w=f2tf(f.w);
    return u;
}

#define TBUF 4608   // 128*36 words per buffer

__global__ void __launch_bounds__(256) gemm_tf32_batch(
    GemmB gb, int Ndim, int Kdim)
{
    extern __shared__ unsigned smemU[];
    unsigned* AsB = smemU;              // [2][128][36]
    unsigned* BsB = smemU + 2*TBUF;     // [2][128][36]

    const int z = blockIdx.z;
    const float* A    = gb.A[z];
    const float* Bw   = gb.W[z];
    const float* bias = gb.bias[z];
    float*       Cm   = gb.C[z];

    const int tid  = threadIdx.x;
    const int warp = tid >> 5, lane = tid & 31;
    const int gid  = lane >> 2, tig = lane & 3;
    const int bm = blockIdx.y*128, bn = blockIdx.x*128;
    const int wm = (warp >> 1)*32;     // 0,32,64,96
    const int wn = (warp & 1)*64;      // 0,64

    const int lr = tid >> 2;           // 0..63 (load row)
    const int lc = (tid & 3) << 3;     // 0,8,16,24 (k offset)

    float acc[2][8][4];
    #pragma unroll
    for (int mt=0; mt<2; mt++)
        #pragma unroll
        for (int nt=0; nt<8; nt++)
            #pragma unroll
            for (int r=0; r<4; r++) acc[mt][nt][r] = 0.f;

    const float* Aptr = A  + (size_t)(bm+lr)*Kdim + lc;
    const float* Bptr = Bw + (size_t)(bn+lr)*Kdim + lc;

    float4 ra[4], rb[4];
    ra[0] = *(const float4*)(Aptr);
    ra[1] = *(const float4*)(Aptr + 4);
    ra[2] = *(const float4*)(Aptr + (size_t)64*Kdim);
    ra[3] = *(const float4*)(Aptr + (size_t)64*Kdim + 4);
    rb[0] = *(const float4*)(Bptr);
    rb[1] = *(const float4*)(Bptr + 4);
    rb[2] = *(const float4*)(Bptr + (size_t)64*Kdim);
    rb[3] = *(const float4*)(Bptr + (size_t)64*Kdim + 4);

    const int ntiles = Kdim >> 5;
    for (int it=0; it<ntiles; it++){
        const int bo = (it & 1)*TBUF;
        unsigned* As = AsB + bo;
        unsigned* Bs = BsB + bo;
        // store current tile (regs -> smem[buf]); safe: all reads of this
        // buffer finished before the PREVIOUS barrier (buffer parity)
        *(uint4*)&As[lr*36 + lc]        = f2tf4(ra[0]);
        *(uint4*)&As[lr*36 + lc+4]      = f2tf4(ra[1]);
        *(uint4*)&As[(lr+64)*36 + lc]   = f2tf4(ra[2]);
        *(uint4*)&As[(lr+64)*36 + lc+4] = f2tf4(ra[3]);
        *(uint4*)&Bs[lr*36 + lc]        = f2tf4(rb[0]);
        *(uint4*)&Bs[lr*36 + lc+4]      = f2tf4(rb[1]);
        *(uint4*)&Bs[(lr+64)*36 + lc]   = f2tf4(rb[2]);
        *(uint4*)&Bs[(lr+64)*36 + lc+4] = f2tf4(rb[3]);

        if (it+1 < ntiles){             // prefetch next tile (global)
            int kn = (it+1) << 5;
            ra[0] = *(const float4*)(Aptr + kn);
            ra[1] = *(const float4*)(Aptr + kn + 4);
            ra[2] = *(const float4*)(Aptr + (size_t)64*Kdim + kn);
            ra[3] = *(const float4*)(Aptr + (size_t)64*Kdim + kn + 4);
            rb[0] = *(const float4*)(Bptr + kn);
            rb[1] = *(const float4*)(Bptr + kn + 4);
            rb[2] = *(const float4*)(Bptr + (size_t)64*Kdim + kn);
            rb[3] = *(const float4*)(Bptr + (size_t)64*Kdim + kn + 4);
        }
        __syncthreads();                // stores visible; begin mma on buf

        #pragma unroll
        for (int ks=0; ks<4; ks++){
            const int kt = ks*8 + tig;
            unsigned af[2][4];
            #pragma unroll
            for (int mt=0; mt<2; mt++){
                int m = wm + mt*16;
                af[mt][0] = As[(m+gid  )*36 + kt];
                af[mt][1] = As[(m+gid+8)*36 + kt];
                af[mt][2] = As[(m+gid  )*36 + kt+4];
                af[mt][3] = As[(m+gid+8)*36 + kt+4];
            }
            unsigned bf[8][2];
            #pragma unroll
            for (int nt=0; nt<8; nt++){
                int n = wn + nt*8;
                bf[nt][0] = Bs[(n+gid)*36 + kt];
                bf[nt][1] = Bs[(n+gid)*36 + kt+4];
            }
            #pragma unroll
            for (int mt=0; mt<2; mt++)
                #pragma unroll
                for (int nt=0; nt<8; nt++){
                    asm volatile(
                      "mma.sync.aligned.m16n8k8.row.col.f32.tf32.tf32.f32 "
                      "{%0,%1,%2,%3}, {%4,%5,%6,%7}, {%8,%9}, {%0,%1,%2,%3};\n"
                      : "+f"(acc[mt][nt][0]), "+f"(acc[mt][nt][1]),
                        "+f"(acc[mt][nt][2]), "+f"(acc[mt][nt][3])
                      : "r"(af[mt][0]), "r"(af[mt][1]),
                        "r"(af[mt][2]), "r"(af[mt][3]),
                        "r"(bf[nt][0]), "r"(bf[nt][1]));
                }
        }
    }

    #pragma unroll
    for (int mt=0; mt<2; mt++){
        int row0 = bm + wm + mt*16 + gid;
        #pragma unroll
        for (int nt=0; nt<8; nt++){
            int col = bn + wn + nt*8 + tig*2;
            float b0 = bias[col], b1 = bias[col+1];
            float2 v0 = make_float2(acc[mt][nt][0]+b0, acc[mt][nt][1]+b1);
            float2 v1 = make_float2(acc[mt][nt][2]+b0, acc[mt][nt][3]+b1);
            *(float2*)&Cm[(size_t)row0*Ndim + col]     = v0;
            *(float2*)&Cm[(size_t)(row0+8)*Ndim + col] = v1;
        }
    }
}

// ---------------------------------------------------------------------------
// 2b. Tiled fp32 GEMM (alpha path: precision-sensitive, K=64 only)
//     EPI: 0 = none, 1 = sigmoid then clamp [0.1, 1.0]
// ---------------------------------------------------------------------------
template<int EPI>
__global__ void __launch_bounds__(256) gemm_tn(
    const float* __restrict__ A, const float* __restrict__ Bw,
    const float* __restrict__ bias, float* __restrict__ Cm,
    int Mdim, int Ndim, int Kdim)
{
    __shared__ float As[16][132];
    __shared__ float Bs[16][132];
    const int tid = threadIdx.x;
    const int bm = blockIdx.y * 128;
    const int bn = blockIdx.x * 128;
    const int lr = tid >> 2;
    const int lc = (tid & 3) << 2;
    const int tr = (tid >> 4) << 3;
    const int tc = (tid & 15) << 3;

    float acc[8][8];
    #pragma unroll
    for (int i=0;i<8;i++)
        #pragma unroll
        for (int j=0;j<8;j++) acc[i][j]=0.f;

    const float* Aptr = A  + (size_t)(bm+lr)*Kdim + lc;
    const float* Bptr = Bw + (size_t)(bn+lr)*Kdim + lc;

    for (int k0=0;k0<Kdim;k0+=16){
        float4 a0 = *(const float4*)(Aptr + k0);
        float4 a1 = *(const float4*)(Aptr + (size_t)64*Kdim + k0);
        float4 b0 = *(const float4*)(Bptr + k0);
        float4 b1 = *(const float4*)(Bptr + (size_t)64*Kdim + k0);
        __syncthreads();
        As[lc+0][lr]=a0.x; As[lc+1][lr]=a0.y; As[lc+2][lr]=a0.z; As[lc+3][lr]=a0.w;
        As[lc+0][lr+64]=a1.x; As[lc+1][lr+64]=a1.y; As[lc+2][lr+64]=a1.z; As[lc+3][lr+64]=a1.w;
        Bs[lc+0][lr]=b0.x; Bs[lc+1][lr]=b0.y; Bs[lc+2][lr]=b0.z; Bs[lc+3][lr]=b0.w;
        Bs[lc+0][lr+64]=b1.x; Bs[lc+1][lr+64]=b1.y; Bs[lc+2][lr+64]=b1.z; Bs[lc+3][lr+64]=b1.w;
        __syncthreads();
        #pragma unroll
        for (int kk=0;kk<16;kk++){
            float4 ar0 = *(const float4*)&As[kk][tr];
            float4 ar1 = *(const float4*)&As[kk][tr+4];
            float4 br0 = *(const float4*)&Bs[kk][tc];
            float4 br1 = *(const float4*)&Bs[kk][tc+4];
            float av[8] = {ar0.x,ar0.y,ar0.z,ar0.w, ar1.x,ar1.y,ar1.z,ar1.w};
            float bv2[8] = {br0.x,br0.y,br0.z,br0.w, br1.x,br1.y,br1.z,br1.w};
            #pragma unroll
            for (int i=0;i<8;i++)
                #pragma unroll
                for (int j=0;j<8;j++) acc[i][j] += av[i]*bv2[j];
        }
    }
    #pragma unroll
    for (int i=0;i<8;i++){
        #pragma unroll
        for (int j=0;j<8;j++){
            float v = acc[i][j] + bias[bn+tc+j];
            if (EPI==1){ v = 1.f/(1.f+__expf(-v)); v = fminf(fmaxf(v, 0.1f), 1.0f); }
            Cm[(size_t)(bm+tr+i)*Ndim + bn + tc + j] = v;
        }
    }
}

// ---------------------------------------------------------------------------
// 3. Fused gate projections from raw x (one pass over x), float4 dots:
//    HA = silu(x@Wad^T+bad)  -> global (feeds alpha GEMM)
//    HG = silu(x@Wgd^T+bgd)  -> shared only
//    BE = min(sigmoid(x@Wbeta^T+bbeta),1) -> global
//    GG = sigmoid(HG@Wgu^T+bgu) -> global   (fused second stage)
// ---------------------------------------------------------------------------
__global__ void gates_kernel(const float* __restrict__ x,
    const float* __restrict__ Wad,  const float* __restrict__ bad,
    const float* __restrict__ Wgd,  const float* __restrict__ bgd,
    const float* __restrict__ Wbe,  const float* __restrict__ bbe,
    const float* __restrict__ Wgu,  const float* __restrict__ bgu,
    float* __restrict__ HA, float* __restrict__ BE, float* __restrict__ GG)
{
    __shared__ float srow[DM];
    __shared__ float sHG[RR];
    int row = blockIdx.x;
    {
        float4 v = *(const float4*)(x + (size_t)row*DM + threadIdx.x*4);
        *(float4*)&srow[threadIdx.x*4] = v;
    }
    __syncthreads();
    int warp = threadIdx.x>>5, lane = threadIdx.x&31;
    for (int n=warp; n<144; n+=8){
        const float* w; float b; int kind;
        if (n < 64)      { w = Wad + (size_t)n*DM;       b = bad[n];     kind=0; }
        else if (n <128) { w = Wgd + (size_t)(n-64)*DM;  b = bgd[n-64];  kind=1; }
        else             { w = Wbe + (size_t)(n-128)*DM; b = bbe[n-128]; kind=2; }
        float s=0.f;
        #pragma unroll
        for (int k8=0;k8<8;k8++){
            int k = (k8*32 + lane)*4;
            float4 a = *(const float4*)&srow[k];
            float4 bw = *(const float4*)&w[k];
            s += a.x*bw.x + a.y*bw.y + a.z*bw.z + a.w*bw.w;
        }
        #pragma unroll
        for (int off=16;off>0;off>>=1) s += __shfl_down_sync(0xffffffffu, s, off);
        if (lane==0){
            float v = s + b;
            if (kind==0){
                v = v/(1.f+__expf(-v));
                HA[(size_t)row*RR+n] = v;
            } else if (kind==1){
                v = v/(1.f+__expf(-v));
                sHG[n-64] = v;
            } else {
                v = fminf(1.f/(1.f+__expf(-v)), 1.0f);
                BE[(size_t)row*HH+(n-128)] = v;
            }
        }
    }
    __syncthreads();
    // g = sigmoid(HG @ Wgu^T + bgu), HG in shared
    for (int n2=warp; n2<HH; n2+=8){
        float s = sHG[lane]*Wgu[(size_t)n2*RR+lane]
                + sHG[lane+32]*Wgu[(size_t)n2*RR+lane+32];
        #pragma unroll
        for (int off=16;off>0;off>>=1) s += __shfl_down_sync(0xffffffffu, s, off);
        if (lane==0)
            GG[(size_t)row*HH+n2] = 1.f/(1.f+__expf(-(s + bgu[n2])));
    }
}

// ---------------------------------------------------------------------------
// 4. Chunked delta-rule recurrence. One block per (b,h), 512 threads.
//    sK/sV/sA use stride 64 (16B-aligned rows) so the sequential scan can
//    read k/a as LDS.128 — cuts scan shared-load instruction count 17->5
//    per thread per step. sQ/scl/ske/sS/sO/sqd/sAb keep stride 65.
// ---------------------------------------------------------------------------
__global__ void __launch_bounds__(512,1) recurrence_kernel(
    const float* __restrict__ Qm, const float* __restrict__ Km,
    const float* __restrict__ Vm, const float* __restrict__ Al,
    const float* __restrict__ Be, const float* __restrict__ GG,
    const float* __restrict__ rmsw, float* __restrict__ Om)
{
    extern __shared__ float sh[];
    float* sQ  = sh;            // 64x65
    float* sK  = sQ  + 64*65;   // 64x64 (aligned rows)
    float* sV  = sK  + 64*64;   // 64x64
    float* sA  = sV  + 64*64;   // 64x64
    float* scl = sA  + 64*64;   // 64x65
    float* ske = scl + 64*65;   // 64x65
    float* sS  = ske + 64*65;   // 64x65
    float* sO  = sS  + 64*65;   // 64x65
    float* sqd = sO  + 64*65;   // 16x65
    float* sAb = sqd + 16*65;   // 16x65
    float* sbet= sAb + 16*65;   // 64
    float* ssum= sbet + 64;     // 64x9 segment totals for cumsum

    const int bh = blockIdx.x;
    const int b  = bh / HH, h = bh % HH;
    const int tid = threadIdx.x;
    const int e  = tid >> 3, dg = tid & 7;
    const int colq = h*DKH;

    float Sreg[8];
    #pragma unroll
    for (int r=0;r<8;r++) Sreg[r]=0.f;

    // --- initial prefetch (chunk 0) into registers ---
    float pq[8], pk[8], pv[8], pa[8], pbet = 0.f;
    #pragma unroll
    for (int r=0;r<8;r++){
        int idx = tid + r*512;
        int t = idx>>6, d = idx&63;
        size_t g = (size_t)(b*TT + t)*DM + colq + d;
        pq[r]=Qm[g]; pk[r]=Km[g]; pv[r]=Vm[g]; pa[r]=Al[g];
    }
    if (tid < CC) pbet = Be[(size_t)(b*TT+tid)*HH + h];

    for (int nc=0; nc<NCH; nc++){
        const int t0 = nc*CC;
        // --- store prefetched tiles ---
        #pragma unroll
        for (int r=0;r<8;r++){
            int idx = tid + r*512;
            int t = idx>>6, d = idx&63;
            sQ[t*65+d]=pq[r];
            sK[t*64+d]=pk[r]; sV[t*64+d]=pv[r]; sA[t*64+d]=pa[r];
        }
        if (tid < CC) sbet[tid] = pbet;
        __syncthreads();

        // --- fused L2-norm of sQ/sK rows + local log-cumsum segments ---
        {
            int tn = tid>>3, ln = tid&7;
            float nq=0.f, nk=0.f;
            #pragma unroll
            for (int r=0;r<8;r++){
                int d = ln*8+r;
                float q = sQ[tn*65+d], k = sK[tn*64+d];
                nq += q*q; nk += k*k;
            }
            nq += __shfl_xor_sync(0xffffffffu, nq, 4, 8);
            nq += __shfl_xor_sync(0xffffffffu, nq, 2, 8);
            nq += __shfl_xor_sync(0xffffffffu, nq, 1, 8);
            nk += __shfl_xor_sync(0xffffffffu, nk, 4, 8);
            nk += __shfl_xor_sync(0xffffffffu, nk, 2, 8);
            nk += __shfl_xor_sync(0xffffffffu, nk, 1, 8);
            float iq = rsqrtf(fmaxf(nq, 1e-6f));
            float ik = rsqrtf(fmaxf(nk, 1e-6f));
            #pragma unroll
            for (int r=0;r<8;r++){
                int d = ln*8+r;
                sQ[tn*65+d] *= iq;
                sK[tn*64+d] *= ik;
            }
        }
        // cumsum segments: thread owns (d2, t-segment sb2 of 8 steps)
        float cv8[8];
        {
            int d2 = tid >> 3, sb2 = tid & 7;
            float run = 0.f;
            #pragma unroll
            for (int r=0;r<8;r++){
                run += __logf(sA[(sb2*8+r)*64 + d2]);
                cv8[r] = run;
            }
            ssum[d2*9 + sb2] = run;
        }
        __syncthreads();
        {
            int d2 = tid >> 3, sb2 = tid & 7;
            float off = 0.f;
            #pragma unroll
            for (int j=0;j<7;j++) if (j < sb2) off += ssum[d2*9 + j];
            #pragma unroll
            for (int r=0;r<8;r++) scl[(sb2*8+r)*65 + d2] = cv8[r] + off;
        }
        // stage S into shared (sS untouched above)
        #pragma unroll
        for (int r=0;r<8;r++) sS[(dg*8+r)*65 + e] = Sreg[r];
        __syncthreads();

        // --- O_inter = Qc @ S ---
        {
            int oe = tid & 63, i0 = (tid>>6)*8;
            float acc[8];
            #pragma unroll
            for (int i=0;i<8;i++) acc[i]=0.f;
            for (int d=0; d<DKH; d++){
                float sv = sS[d*65+oe];
                #pragma unroll
                for (int i=0;i<8;i++) acc[i] += sQ[(i0+i)*65+d]*sv;
            }
            #pragma unroll
            for (int i=0;i<8;i++) sO[(i0+i)*65+oe]=acc[i];
        }
        __syncthreads();

        // --- intra-chunk decay attention, 4 sub-chunks of 16 rows ---
        for (int I=0;I<4;I++){
            int rbase = I*16 - 1;          // re-base row (-1 => cl = 0)
            int jmax  = I*16 + 16;
            for (int idx=tid; idx<jmax*64; idx+=512){
                int j=idx>>6, d=idx&63;
                float cb = (rbase>=0)? scl[rbase*65+d] : 0.f;
                ske[j*65+d] = sK[j*64+d]*sbet[j]*__expf(cb - scl[j*65+d]);
            }
            for (int idx=tid; idx<16*64; idx+=512){
                int ii=idx>>6, d=idx&63;
                float cb = (rbase>=0)? scl[rbase*65+d] : 0.f;
                sqd[ii*65+d] = sQ[(I*16+ii)*65+d]*__expf(scl[(I*16+ii)*65+d] - cb);
            }
            __syncthreads();
            for (int idx=tid; idx<1024; idx+=512){
                int ii=idx>>6, j=idx&63;
                float s = 0.f;
                if (j <= I*16+ii){
                    #pragma unroll 16
                    for (int d=0;d<64;d++) s += sqd[ii*65+d]*ske[j*65+d];
                }
                sAb[ii*65+j]=s;
            }
            __syncthreads();
            {
                int oe = tid&63, ii0 = tid>>6;
                float a0=0.f, a1=0.f;
                for (int j=0;j<jmax;j++){
                    float vv = sV[j*64+oe];
                    a0 += sAb[ii0*65+j]*vv;
                    a1 += sAb[(ii0+8)*65+j]*vv;
                }
                sO[(I*16+ii0)*65+oe]   += a0;
                sO[(I*16+ii0+8)*65+oe] += a1;
            }
            __syncthreads();
        }

        // --- write O chunk with fused RMSNorm * rms_w * gate ---
        {
            int tn = tid>>3, ln = tid&7;
            float vv8[8]; float s = 0.f;
            #pragma unroll
            for (int r=0;r<8;r++){
                float v = sO[tn*65 + ln*8 + r];
                vv8[r]=v; s += v*v;
            }
            s += __shfl_xor_sync(0xffffffffu, s, 4, 8);
            s += __shfl_xor_sync(0xffffffffu, s, 2, 8);
            s += __shfl_xor_sync(0xffffffffu, s, 1, 8);
            float scale = rsqrtf(s*(1.0f/DVH) + 1e-6f);
            float gg = GG[(size_t)(b*TT+t0+tn)*HH + h];
            size_t gb = (size_t)(b*TT+t0+tn)*DM + h*DVH + ln*8;
            #pragma unroll
            for (int r=0;r<8;r++)
                Om[gb + r] = vv8[r]*scale*rmsw[h*DVH + ln*8 + r]*gg;
        }

        // --- prefetch next chunk (hidden behind the scan) ---
        if (nc+1 < NCH){
            const int t1 = (nc+1)*CC;
            #pragma unroll
            for (int r=0;r<8;r++){
                int idx = tid + r*512;
                int t = idx>>6, d = idx&63;
                size_t g = (size_t)(b*TT + t1 + t)*DM + colq + d;
                pq[r]=Qm[g]; pk[r]=Km[g]; pv[r]=Vm[g]; pa[r]=Al[g];
            }
            if (tid < CC) pbet = Be[(size_t)(b*TT+t1+tid)*HH + h];
        }

        // --- exact sequential state update over the chunk ---
        // k/a rows are 16B-aligned (stride 64): LDS.128 x2 each.
        for (int t=0;t<CC;t++){
            float bt = sbet[t];
            float vt = sV[t*64+e];
            float4 k0 = *(const float4*)&sK[t*64 + dg*8];
            float4 k1 = *(const float4*)&sK[t*64 + dg*8 + 4];
            float4 a0 = *(const float4*)&sA[t*64 + dg*8];
            float4 a1 = *(const float4*)&sA[t*64 + dg*8 + 4];
            const float* kf = (const float*)&k0;  // k0,k1 contiguous? no —
            // use explicit components to stay safe:
            float kk2[8] = {k0.x,k0.y,k0.z,k0.w, k1.x,k1.y,k1.z,k1.w};
            float aa2[8] = {a0.x,a0.y,a0.z,a0.w, a1.x,a1.y,a1.z,a1.w};
            (void)kf;
            float part = 0.f;
            #pragma unroll
            for (int r=0;r<8;r++){
                Sreg[r] *= aa2[r];
                part += kk2[r]*Sreg[r];
            }
            part += __shfl_xor_sync(0xffffffffu, part, 4, 8);
            part += __shfl_xor_sync(0xffffffffu, part, 2, 8);
            part += __shfl_xor_sync(0xffffffffu, part, 1, 8);
            float coef = bt*(vt - part);
            #pragma unroll
            for (int r=0;r<8;r++) Sreg[r] += coef*kk2[r];
        }
        __syncthreads();
    }
}

// ---------------------------------------------------------------------------
// Launcher. Inputs in metadata order:
// 0:x 1:wq_conv 2:bq_conv 3:wk_conv 4:bk_conv 5:wv_conv 6:bv_conv
// 7:Wq 8:bq 9:Wk 10:bk 11:Wv 12:bv 13:Wad 14:bad 15:Wau 16:bau
// 17:Wbeta 18:bbeta 19:rms_w 20:Wgd 21:bgd 22:Wgu 23:bgu 24:Wo 25:bo
// ---------------------------------------------------------------------------
extern "C" void kernel_launch(void* const* d_in, const int* in_sizes, int n_in,
                              void* d_out, int out_size)
{
    const float* x     = (const float*)d_in[0];
    const float* wqc   = (const float*)d_in[1];
    const float* bqc   = (const float*)d_in[2];
    const float* wkc   = (const float*)d_in[3];
    const float* bkc   = (const float*)d_in[4];
    const float* wvc   = (const float*)d_in[5];
    const float* bvc   = (const float*)d_in[6];
    const float* Wq    = (const float*)d_in[7];
    const float* bq    = (const float*)d_in[8];
    const float* Wk    = (const float*)d_in[9];
    const float* bk    = (const float*)d_in[10];
    const float* Wv    = (const float*)d_in[11];
    const float* bv    = (const float*)d_in[12];
    const float* Wad   = (const float*)d_in[13];
    const float* bad   = (const float*)d_in[14];
    const float* Wau   = (const float*)d_in[15];
    const float* bau   = (const float*)d_in[16];
    const float* Wbeta = (const float*)d_in[17];
    const float* bbeta = (const float*)d_in[18];
    const float* rms_w = (const float*)d_in[19];
    const float* Wgd   = (const float*)d_in[20];
    const float* bgd   = (const float*)d_in[21];
    const float* Wgu   = (const float*)d_in[22];
    const float* bgu   = (const float*)d_in[23];
    const float* Wo    = (const float*)d_in[24];
    const float* bo    = (const float*)d_in[25];
    float* out = (float*)d_out;

    float* sc = nullptr;
    cudaGetSymbolAddress((void**)&sc, g_scratch);
    const size_t SZ = (size_t)MR*DM;
    float* CQ = sc;          float* CK = sc+SZ;    float* CV = sc+2*SZ;
    float* QB = sc+3*SZ;     float* KB = sc+4*SZ;  float* VB = sc+5*SZ;
    float* AL = sc+6*SZ;     float* OA = sc+7*SZ;
    float* HA = sc+8*SZ;
    float* BE = HA + (size_t)2*MR*RR;
    float* GG = BE + (size_t)MR*HH;

    // conv + silu pre-activations (float4 vectorized)
    conv_silu_kernel<<<(MR*DM/4)/256, 256>>>(x, wqc,bqc, wkc,bkc, wvc,bvc,
                                             CQ,CK,CV);

    // fused gate branches from raw x (alpha-down, g-down + g-up, beta)
    gates_kernel<<<MR,256>>>(x, Wad,bad, Wgd,bgd, Wbeta,bbeta, Wgu,bgu,
                             HA, BE, GG);

    // big projections: TF32 tensor cores, double-buffered, Q/K/V batched
    const int gemm_smem = 2*2*TBUF*(int)sizeof(unsigned);   // 73728 B
    cudaFuncSetAttribute(gemm_tf32_batch,
                         cudaFuncAttributeMaxDynamicSharedMemorySize, gemm_smem);
    {
        GemmB gq;
        gq.A[0]=CQ;  gq.A[1]=CK;  gq.A[2]=CV;
        gq.W[0]=Wq;  gq.W[1]=Wk;  gq.W[2]=Wv;
        gq.bias[0]=bq; gq.bias[1]=bk; gq.bias[2]=bv;
        gq.C[0]=QB;  gq.C[1]=KB;  gq.C[2]=VB;
        dim3 g3(DM/128, MR/128, 3);
        gemm_tf32_batch<<<g3, 256, gemm_smem>>>(gq, DM, DM);
    }
    // alpha path stays fp32 (errors amplified through 64-step log-cumsum-exp)
    dim3 gblk(DM/128, MR/128);
    gemm_tn<1><<<gblk,256>>>(HA, Wau, bau, AL, MR, DM, RR);

    // chunked delta-rule recurrence (fused l2norm + rms/gate epilogue)
    size_t smem = (size_t)(64*65 + 3*64*64 + 4*64*65 + 2*16*65 + 64 + 64*9)
                  * sizeof(float);
    cudaFuncSetAttribute(recurrence_kernel,
                         cudaFuncAttributeMaxDynamicSharedMemorySize, (int)smem);
    recurrence_kernel<<<BHN, 512, smem>>>(QB, KB, VB, AL, BE, GG, rms_w, OA);

    // output projection (TF32, same batched kernel with z=1)
    {
        GemmB go;
        go.A[0]=OA;  go.A[1]=OA;  go.A[2]=OA;
        go.W[0]=Wo;  go.W[1]=Wo;  go.W[2]=Wo;
        go.bias[0]=bo; go.bias[1]=bo; go.bias[2]=bo;
        go.C[0]=out; go.C[1]=out; go.C[2]=out;
        dim3 g1(DM/128, MR/128, 1);
        gemm_tf32_batch<<<g1, 256, gemm_smem>>>(go, DM, DM);
    }
}

// round 14
// speedup vs baseline: 1.6429x; 1.6429x over previous
#include <cuda_runtime.h>
#include <math.h>

// ---------------------------------------------------------------------------
// Problem constants (reference: D_MODEL=1024, H=16, DK=DV=64, R=64, C=64,
// KW=4, B=2, T=2048)
// ---------------------------------------------------------------------------
#define DM   1024
#define HH   16
#define DKH  64
#define DVH  64
#define RR   64
#define CC   64
#define KWW  4
#define BB   2
#define TT   2048
#define MR   (BB*TT)        // 4096 rows (b,t)
#define BHN  (BB*HH)        // 32
#define NCH  (TT/CC)        // 32 chunks

// Scratch: 8 big [4096,1024] buffers + hA [4096,64]x2 + beta,g [4096,16]
__device__ float g_scratch[(size_t)8*MR*DM + (size_t)2*MR*RR + (size_t)2*MR*HH];

// ---------------------------------------------------------------------------
// 1. Causal depthwise conv (KW=4) + SiLU, float4-vectorized
// ---------------------------------------------------------------------------
__global__ void conv_silu_kernel(const float* __restrict__ x,
    const float* __restrict__ wq, const float* __restrict__ bq,
    const float* __restrict__ wk, const float* __restrict__ bk,
    const float* __restrict__ wv, const float* __restrict__ bv,
    float* __restrict__ cq, float* __restrict__ ck, float* __restrict__ cv)
{
    int g4 = blockIdx.x*blockDim.x + threadIdx.x;
    if (g4 >= MR*DM/4) return;
    int base = g4*4;
    int d4  = base & (DM-1);
    int row = base >> 10;
    int t   = row & (TT-1);

    float4 xs4[KWW];
    #pragma unroll
    for (int j=0;j<KWW;j++){
        int tt2 = t - (KWW-1) + j;
        if (tt2 >= 0) xs4[j] = *(const float4*)(x + base + (j-(KWW-1))*DM);
        else          xs4[j] = make_float4(0.f,0.f,0.f,0.f);
    }
    const float* xsf = (const float*)xs4;

    float4 oq, ok, ov;
    float* oqf = (float*)&oq; float* okf = (float*)&ok; float* ovf = (float*)&ov;
    #pragma unroll
    for (int i=0;i<4;i++){
        int d = d4 + i;
        float yq=bq[d], yk=bk[d], yv=bv[d];
        #pragma unroll
        for (int j=0;j<KWW;j++){
            float xv = xsf[j*4+i];
            yq += xv*wq[d*KWW+j];
            yk += xv*wk[d*KWW+j];
            yv += xv*wv[d*KWW+j];
        }
        oqf[i] = yq / (1.f + __expf(-yq));
        okf[i] = yk / (1.f + __expf(-yk));
        ovf[i] = yv / (1.f + __expf(-yv));
    }
    *(float4*)(cq + base) = oq;
    *(float4*)(ck + base) = ok;
    *(float4*)(cv + base) = ov;
}

// ---------------------------------------------------------------------------
// 2a. TF32 tensor-core GEMM batch (unchanged from passing R13)
// ---------------------------------------------------------------------------
struct GemmB {
    const float* A[3];
    const float* W[3];
    const float* bias[3];
    float*       C[3];
};

__device__ __forceinline__ unsigned f2tf(float f){
    unsigned u; asm("cvt.rna.tf32.f32 %0, %1;" : "=r"(u) : "f"(f)); return u;
}
__device__ __forceinline__ uint4 f2tf4(float4 f){
    uint4 u; u.x=f2tf(f.x); u.y=f2tf(f.y); u.z=f2tf(f.z); u.w=f2tf(f.w);
    return u;
}

#define TBUF 4608   // 128*36 words per buffer

__global__ void __launch_bounds__(256) gemm_tf32_batch(
    GemmB gb, int Ndim, int Kdim)
{
    extern __shared__ unsigned smemU[];
    unsigned* AsB = smemU;
    unsigned* BsB = smemU + 2*TBUF;

    const int z = blockIdx.z;
    const float* A    = gb.A[z];
    const float* Bw   = gb.W[z];
    const float* bias = gb.bias[z];
    float*       Cm   = gb.C[z];

    const int tid  = threadIdx.x;
    const int warp = tid >> 5, lane = tid & 31;
    const int gid  = lane >> 2, tig = lane & 3;
    const int bm = blockIdx.y*128, bn = blockIdx.x*128;
    const int wm = (warp >> 1)*32;
    const int wn = (warp & 1)*64;

    const int lr = tid >> 2;
    const int lc = (tid & 3) << 3;

    float acc[2][8][4];
    #pragma unroll
    for (int mt=0; mt<2; mt++)
        #pragma unroll
        for (int nt=0; nt<8; nt++)
            #pragma unroll
            for (int r=0; r<4; r++) acc[mt][nt][r] = 0.f;

    const float* Aptr = A  + (size_t)(bm+lr)*Kdim + lc;
    const float* Bptr = Bw + (size_t)(bn+lr)*Kdim + lc;

    float4 ra[4], rb[4];
    ra[0] = *(const float4*)(Aptr);
    ra[1] = *(const float4*)(Aptr + 4);
    ra[2] = *(const float4*)(Aptr + (size_t)64*Kdim);
    ra[3] = *(const float4*)(Aptr + (size_t)64*Kdim + 4);
    rb[0] = *(const float4*)(Bptr);
    rb[1] = *(const float4*)(Bptr + 4);
    rb[2] = *(const float4*)(Bptr + (size_t)64*Kdim);
    rb[3] = *(const float4*)(Bptr + (size_t)64*Kdim + 4);

    const int ntiles = Kdim >> 5;
    for (int it=0; it<ntiles; it++){
        const int bo = (it & 1)*TBUF;
        unsigned* As = AsB + bo;
        unsigned* Bs = BsB + bo;
        *(uint4*)&As[lr*36 + lc]        = f2tf4(ra[0]);
        *(uint4*)&As[lr*36 + lc+4]      = f2tf4(ra[1]);
        *(uint4*)&As[(lr+64)*36 + lc]   = f2tf4(ra[2]);
        *(uint4*)&As[(lr+64)*36 + lc+4] = f2tf4(ra[3]);
        *(uint4*)&Bs[lr*36 + lc]        = f2tf4(rb[0]);
        *(uint4*)&Bs[lr*36 + lc+4]      = f2tf4(rb[1]);
        *(uint4*)&Bs[(lr+64)*36 + lc]   = f2tf4(rb[2]);
        *(uint4*)&Bs[(lr+64)*36 + lc+4] = f2tf4(rb[3]);

        if (it+1 < ntiles){
            int kn = (it+1) << 5;
            ra[0] = *(const float4*)(Aptr + kn);
            ra[1] = *(const float4*)(Aptr + kn + 4);
            ra[2] = *(const float4*)(Aptr + (size_t)64*Kdim + kn);
            ra[3] = *(const float4*)(Aptr + (size_t)64*Kdim + kn + 4);
            rb[0] = *(const float4*)(Bptr + kn);
            rb[1] = *(const float4*)(Bptr + kn + 4);
            rb[2] = *(const float4*)(Bptr + (size_t)64*Kdim + kn);
            rb[3] = *(const float4*)(Bptr + (size_t)64*Kdim + kn + 4);
        }
        __syncthreads();

        #pragma unroll
        for (int ks=0; ks<4; ks++){
            const int kt = ks*8 + tig;
            unsigned af[2][4];
            #pragma unroll
            for (int mt=0; mt<2; mt++){
                int m = wm + mt*16;
                af[mt][0] = As[(m+gid  )*36 + kt];
                af[mt][1] = As[(m+gid+8)*36 + kt];
                af[mt][2] = As[(m+gid  )*36 + kt+4];
                af[mt][3] = As[(m+gid+8)*36 + kt+4];
            }
            unsigned bf[8][2];
            #pragma unroll
            for (int nt=0; nt<8; nt++){
                int n = wn + nt*8;
                bf[nt][0] = Bs[(n+gid)*36 + kt];
                bf[nt][1] = Bs[(n+gid)*36 + kt+4];
            }
            #pragma unroll
            for (int mt=0; mt<2; mt++)
                #pragma unroll
                for (int nt=0; nt<8; nt++){
                    asm volatile(
                      "mma.sync.aligned.m16n8k8.row.col.f32.tf32.tf32.f32 "
                      "{%0,%1,%2,%3}, {%4,%5,%6,%7}, {%8,%9}, {%0,%1,%2,%3};\n"
                      : "+f"(acc[mt][nt][0]), "+f"(acc[mt][nt][1]),
                        "+f"(acc[mt][nt][2]), "+f"(acc[mt][nt][3])
                      : "r"(af[mt][0]), "r"(af[mt][1]),
                        "r"(af[mt][2]), "r"(af[mt][3]),
                        "r"(bf[nt][0]), "r"(bf[nt][1]));
                }
        }
    }

    #pragma unroll
    for (int mt=0; mt<2; mt++){
        int row0 = bm + wm + mt*16 + gid;
        #pragma unroll
        for (int nt=0; nt<8; nt++){
            int col = bn + wn + nt*8 + tig*2;
            float b0 = bias[col], b1 = bias[col+1];
            float2 v0 = make_float2(acc[mt][nt][0]+b0, acc[mt][nt][1]+b1);
            float2 v1 = make_float2(acc[mt][nt][2]+b0, acc[mt][nt][3]+b1);
            *(float2*)&Cm[(size_t)row0*Ndim + col]     = v0;
            *(float2*)&Cm[(size_t)(row0+8)*Ndim + col] = v1;
        }
    }
}

// ---------------------------------------------------------------------------
// 2b. Tiled fp32 GEMM (alpha path, unchanged)
// ---------------------------------------------------------------------------
template<int EPI>
__global__ void __launch_bounds__(256) gemm_tn(
    const float* __restrict__ A, const float* __restrict__ Bw,
    const float* __restrict__ bias, float* __restrict__ Cm,
    int Mdim, int Ndim, int Kdim)
{
    __shared__ float As[16][132];
    __shared__ float Bs[16][132];
    const int tid = threadIdx.x;
    const int bm = blockIdx.y * 128;
    const int bn = blockIdx.x * 128;
    const int lr = tid >> 2;
    const int lc = (tid & 3) << 2;
    const int tr = (tid >> 4) << 3;
    const int tc = (tid & 15) << 3;

    float acc[8][8];
    #pragma unroll
    for (int i=0;i<8;i++)
        #pragma unroll
        for (int j=0;j<8;j++) acc[i][j]=0.f;

    const float* Aptr = A  + (size_t)(bm+lr)*Kdim + lc;
    const float* Bptr = Bw + (size_t)(bn+lr)*Kdim + lc;

    for (int k0=0;k0<Kdim;k0+=16){
        float4 a0 = *(const float4*)(Aptr + k0);
        float4 a1 = *(const float4*)(Aptr + (size_t)64*Kdim + k0);
        float4 b0 = *(const float4*)(Bptr + k0);
        float4 b1 = *(const float4*)(Bptr + (size_t)64*Kdim + k0);
        __syncthreads();
        As[lc+0][lr]=a0.x; As[lc+1][lr]=a0.y; As[lc+2][lr]=a0.z; As[lc+3][lr]=a0.w;
        As[lc+0][lr+64]=a1.x; As[lc+1][lr+64]=a1.y; As[lc+2][lr+64]=a1.z; As[lc+3][lr+64]=a1.w;
        Bs[lc+0][lr]=b0.x; Bs[lc+1][lr]=b0.y; Bs[lc+2][lr]=b0.z; Bs[lc+3][lr]=b0.w;
        Bs[lc+0][lr+64]=b1.x; Bs[lc+1][lr+64]=b1.y; Bs[lc+2][lr+64]=b1.z; Bs[lc+3][lr+64]=b1.w;
        __syncthreads();
        #pragma unroll
        for (int kk=0;kk<16;kk++){
            float4 ar0 = *(const float4*)&As[kk][tr];
            float4 ar1 = *(const float4*)&As[kk][tr+4];
            float4 br0 = *(const float4*)&Bs[kk][tc];
            float4 br1 = *(const float4*)&Bs[kk][tc+4];
            float av[8] = {ar0.x,ar0.y,ar0.z,ar0.w, ar1.x,ar1.y,ar1.z,ar1.w};
            float bv2[8] = {br0.x,br0.y,br0.z,br0.w, br1.x,br1.y,br1.z,br1.w};
            #pragma unroll
            for (int i=0;i<8;i++)
                #pragma unroll
                for (int j=0;j<8;j++) acc[i][j] += av[i]*bv2[j];
        }
    }
    #pragma unroll
    for (int i=0;i<8;i++){
        #pragma unroll
        for (int j=0;j<8;j++){
            float v = acc[i][j] + bias[bn+tc+j];
            if (EPI==1){ v = 1.f/(1.f+__expf(-v)); v = fminf(fmaxf(v, 0.1f), 1.0f); }
            Cm[(size_t)(bm+tr+i)*Ndim + bn + tc + j] = v;
        }
    }
}

// ---------------------------------------------------------------------------
// 3. Fused gate projections (unchanged)
// ---------------------------------------------------------------------------
__global__ void gates_kernel(const float* __restrict__ x,
    const float* __restrict__ Wad,  const float* __restrict__ bad,
    const float* __restrict__ Wgd,  const float* __restrict__ bgd,
    const float* __restrict__ Wbe,  const float* __restrict__ bbe,
    const float* __restrict__ Wgu,  const float* __restrict__ bgu,
    float* __restrict__ HA, float* __restrict__ BE, float* __restrict__ GG)
{
    __shared__ float srow[DM];
    __shared__ float sHG[RR];
    int row = blockIdx.x;
    {
        float4 v = *(const float4*)(x + (size_t)row*DM + threadIdx.x*4);
        *(float4*)&srow[threadIdx.x*4] = v;
    }
    __syncthreads();
    int warp = threadIdx.x>>5, lane = threadIdx.x&31;
    for (int n=warp; n<144; n+=8){
        const float* w; float b; int kind;
        if (n < 64)      { w = Wad + (size_t)n*DM;       b = bad[n];     kind=0; }
        else if (n <128) { w = Wgd + (size_t)(n-64)*DM;  b = bgd[n-64];  kind=1; }
        else             { w = Wbe + (size_t)(n-128)*DM; b = bbe[n-128]; kind=2; }
        float s=0.f;
        #pragma unroll
        for (int k8=0;k8<8;k8++){
            int k = (k8*32 + lane)*4;
            float4 a = *(const float4*)&srow[k];
            float4 bw = *(const float4*)&w[k];
            s += a.x*bw.x + a.y*bw.y + a.z*bw.z + a.w*bw.w;
        }
        #pragma unroll
        for (int off=16;off>0;off>>=1) s += __shfl_down_sync(0xffffffffu, s, off);
        if (lane==0){
            float v = s + b;
            if (kind==0){
                v = v/(1.f+__expf(-v));
                HA[(size_t)row*RR+n] = v;
            } else if (kind==1){
                v = v/(1.f+__expf(-v));
                sHG[n-64] = v;
            } else {
                v = fminf(1.f/(1.f+__expf(-v)), 1.0f);
                BE[(size_t)row*HH+(n-128)] = v;
            }
        }
    }
    __syncthreads();
    for (int n2=warp; n2<HH; n2+=8){
        float s = sHG[lane]*Wgu[(size_t)n2*RR+lane]
                + sHG[lane+32]*Wgu[(size_t)n2*RR+lane+32];
        #pragma unroll
        for (int off=16;off>0;off>>=1) s += __shfl_down_sync(0xffffffffu, s, off);
        if (lane==0)
            GG[(size_t)row*HH+n2] = 1.f/(1.f+__expf(-(s + bgu[n2])));
    }
}

// ---------------------------------------------------------------------------
// 4a. R1: per-(bh,chunk) PARALLEL kernel. grid = BHN*NCH = 1024 blocks.
//     - loads chunk, L2-norms Q/K (writes normalized Q back to Qm),
//     - decay cumsum, intra-chunk decay attention -> OI,
//     - 64-step affine transition scan: T_c = prod (I-b k k^T)diag(a),
//       M_c = scan from S=0.  Writes T_c TRANSPOSED (G[d'][d]) and M_c.
// ---------------------------------------------------------------------------
__global__ void __launch_bounds__(512,1) chunk_kernel(
    float* __restrict__ Qm, const float* __restrict__ Km,
    const float* __restrict__ Vm, const float* __restrict__ Al,
    const float* __restrict__ Be,
    float* __restrict__ OI, float* __restrict__ Tg, float* __restrict__ Mg)
{
    extern __shared__ float sh[];
    float* sQ  = sh;            // 64x65
    float* sK  = sQ  + 64*65;   // 64x64 (16B-aligned rows)
    float* sV  = sK  + 64*64;   // 64x64
    float* sA  = sV  + 64*64;   // 64x64
    float* scl = sA  + 64*64;   // 64x65
    float* ske = scl + 64*65;   // 64x65
    float* sO  = ske + 64*65;   // 64x65
    float* sqd = sO  + 64*65;   // 16x65
    float* sAb = sqd + 16*65;   // 16x65
    float* sbet= sAb + 16*65;   // 64
    float* ssum= sbet + 64;     // 64x9

    const int blk = blockIdx.x;
    const int bh = blk >> 5, nc = blk & 31;   // NCH = 32
    const int b  = bh / HH, h = bh % HH;
    const int tid = threadIdx.x;
    const int colq = h*DKH;
    const int t0 = nc*CC;

    // --- load chunk tiles ---
    #pragma unroll
    for (int r=0;r<8;r++){
        int idx = tid + r*512;
        int t = idx>>6, d = idx&63;
        size_t g = (size_t)(b*TT + t0 + t)*DM + colq + d;
        sQ[t*65+d]=Qm[g]; sK[t*64+d]=Km[g]; sV[t*64+d]=Vm[g]; sA[t*64+d]=Al[g];
    }
    if (tid < CC) sbet[tid] = Be[(size_t)(b*TT+t0+tid)*HH + h];
    __syncthreads();

    // --- L2-norm Q/K rows; write normalized Q back to global ---
    {
        int tn = tid>>3, ln = tid&7;
        float nq=0.f, nk=0.f;
        #pragma unroll
        for (int r=0;r<8;r++){
            int d = ln*8+r;
            float q = sQ[tn*65+d], k = sK[tn*64+d];
            nq += q*q; nk += k*k;
        }
        nq += __shfl_xor_sync(0xffffffffu, nq, 4, 8);
        nq += __shfl_xor_sync(0xffffffffu, nq, 2, 8);
        nq += __shfl_xor_sync(0xffffffffu, nq, 1, 8);
        nk += __shfl_xor_sync(0xffffffffu, nk, 4, 8);
        nk += __shfl_xor_sync(0xffffffffu, nk, 2, 8);
        nk += __shfl_xor_sync(0xffffffffu, nk, 1, 8);
        float iq = rsqrtf(fmaxf(nq, 1e-6f));
        float ik = rsqrtf(fmaxf(nk, 1e-6f));
        size_t gq = (size_t)(b*TT+t0+tn)*DM + colq;
        #pragma unroll
        for (int r=0;r<8;r++){
            int d = ln*8+r;
            float qn = sQ[tn*65+d]*iq;
            sQ[tn*65+d] = qn;
            Qm[gq + d] = qn;           // normalized Q for combine kernel
            sK[tn*64+d] *= ik;
        }
    }
    // --- cumsum of log(alpha): register-segment scan ---
    float cv8[8];
    {
        int d2 = tid >> 3, sb2 = tid & 7;
        float run = 0.f;
        #pragma unroll
        for (int r=0;r<8;r++){
            run += __logf(sA[(sb2*8+r)*64 + d2]);
            cv8[r] = run;
        }
        ssum[d2*9 + sb2] = run;
    }
    __syncthreads();
    {
        int d2 = tid >> 3, sb2 = tid & 7;
        float off = 0.f;
        #pragma unroll
        for (int j=0;j<7;j++) if (j < sb2) off += ssum[d2*9 + j];
        #pragma unroll
        for (int r=0;r<8;r++) scl[(sb2*8+r)*65 + d2] = cv8[r] + off;
    }
    __syncthreads();

    // --- intra-chunk decay attention, 4 sub-chunks of 16 rows ---
    for (int I=0;I<4;I++){
        int rbase = I*16 - 1;
        int jmax  = I*16 + 16;
        for (int idx=tid; idx<jmax*64; idx+=512){
            int j=idx>>6, d=idx&63;
            float cb = (rbase>=0)? scl[rbase*65+d] : 0.f;
            ske[j*65+d] = sK[j*64+d]*sbet[j]*__expf(cb - scl[j*65+d]);
        }
        for (int idx=tid; idx<16*64; idx+=512){
            int ii=idx>>6, d=idx&63;
            float cb = (rbase>=0)? scl[rbase*65+d] : 0.f;
            sqd[ii*65+d] = sQ[(I*16+ii)*65+d]*__expf(scl[(I*16+ii)*65+d] - cb);
        }
        __syncthreads();
        for (int idx=tid; idx<1024; idx+=512){
            int ii=idx>>6, j=idx&63;
            float s = 0.f;
            if (j <= I*16+ii){
                #pragma unroll 16
                for (int d=0;d<64;d++) s += sqd[ii*65+d]*ske[j*65+d];
            }
            sAb[ii*65+j]=s;
        }
        __syncthreads();
        {
            int oe = tid&63, ii0 = tid>>6;
            float a0=0.f, a1=0.f;
            for (int j=0;j<jmax;j++){
                float vv = sV[j*64+oe];
                a0 += sAb[ii0*65+j]*vv;
                a1 += sAb[(ii0+8)*65+j]*vv;
            }
            sO[(I*16+ii0)*65+oe]   = a0;   // assignment (no O_inter here)
            sO[(I*16+ii0+8)*65+oe] = a1;
        }
        __syncthreads();
    }

    // --- write intra O ---
    #pragma unroll
    for (int r=0;r<8;r++){
        int idx = tid + r*512;
        int t = idx>>6, d = idx&63;
        OI[(size_t)(b*TT+t0+t)*DM + colq + d] = sO[t*65+d];
    }

    // --- affine transition scan: thread (x=tid>>3, dg=tid&7) owns
    //     T[dg*8+r][x] and M[dg*8+r][x] for r=0..7 ---
    {
        const int x = tid >> 3, dg = tid & 7;
        float Tr[8], Mr[8];
        #pragma unroll
        for (int r=0;r<8;r++){
            Tr[r] = (dg*8+r == x) ? 1.f : 0.f;
            Mr[r] = 0.f;
        }
        for (int t=0;t<CC;t++){
            float bt = sbet[t];
            float vt = sV[t*64+x];
            float4 k0 = *(const float4*)&sK[t*64 + dg*8];
            float4 k1 = *(const float4*)&sK[t*64 + dg*8 + 4];
            float4 a0 = *(const float4*)&sA[t*64 + dg*8];
            float4 a1 = *(const float4*)&sA[t*64 + dg*8 + 4];
            float kk[8] = {k0.x,k0.y,k0.z,k0.w, k1.x,k1.y,k1.z,k1.w};
            float aa[8] = {a0.x,a0.y,a0.z,a0.w, a1.x,a1.y,a1.z,a1.w};
            float pT=0.f, pM=0.f;
            #pragma unroll
            for (int r=0;r<8;r++){
                Tr[r] *= aa[r];  pT += kk[r]*Tr[r];
                Mr[r] *= aa[r];  pM += kk[r]*Mr[r];
            }
            pT += __shfl_xor_sync(0xffffffffu, pT, 4, 8);
            pT += __shfl_xor_sync(0xffffffffu, pT, 2, 8);
            pT += __shfl_xor_sync(0xffffffffu, pT, 1, 8);
            pM += __shfl_xor_sync(0xffffffffu, pM, 4, 8);
            pM += __shfl_xor_sync(0xffffffffu, pM, 2, 8);
            pM += __shfl_xor_sync(0xffffffffu, pM, 1, 8);
            float cT = -bt*pT;
            float cM =  bt*(vt - pM);
            #pragma unroll
            for (int r=0;r<8;r++){
                Tr[r] += kk[r]*cT;
                Mr[r] += kk[r]*cM;
            }
        }
        size_t ofs = (size_t)blk * 4096;
        // store T transposed: G[x][d] = T[d][x]  (rows 16B aligned)
        float4 g0 = make_float4(Tr[0],Tr[1],Tr[2],Tr[3]);
        float4 g1 = make_float4(Tr[4],Tr[5],Tr[6],Tr[7]);
        *(float4*)&Tg[ofs + (size_t)x*64 + dg*8]     = g0;
        *(float4*)&Tg[ofs + (size_t)x*64 + dg*8 + 4] = g1;
        // store M row-major: M[d][e]
        #pragma unroll
        for (int r=0;r<8;r++)
            Mg[ofs + (size_t)(dg*8+r)*64 + x] = Mr[r];
    }
}

// ---------------------------------------------------------------------------
// 4b. R2: sequential combine. grid = BHN = 32 blocks, 512 threads.
//     Per chunk: O = Q_c @ S + OI -> RMS*rms_w*gate epilogue -> Om;
//     then S <- T_c S + M_c.  Thread (c=tid&63, rg=tid>>6) owns
//     rows rg*8..rg*8+7, column c.
// ---------------------------------------------------------------------------
__global__ void __launch_bounds__(512,1) combine_kernel(
    const float* __restrict__ Qm, const float* __restrict__ Tg,
    const float* __restrict__ Mg, const float* __restrict__ OI,
    const float* __restrict__ GG, const float* __restrict__ rmsw,
    float* __restrict__ Om)
{
    extern __shared__ float sh[];
    float* sS  = sh;            // 64x65 (S_old, col layout)
    float* sG  = sS  + 64*65;   // 64x64 (T transposed)
    float* sQT = sG  + 64*64;   // 64x68 (Q transposed, 16B-aligned rows)
    float* sO  = sQT + 64*68;   // 64x65

    const int bh = blockIdx.x;
    const int b  = bh / HH, h = bh % HH;
    const int tid = threadIdx.x;
    const int c  = tid & 63, rg = tid >> 6;   // col e=c, rows rg*8..+7
    const int colq = h*DKH;

    float Sreg[8];
    #pragma unroll
    for (int r=0;r<8;r++) Sreg[r]=0.f;

    for (int nc=0; nc<NCH; nc++){
        const int t0 = nc*CC;
        const size_t ofs = ((size_t)bh*NCH + nc)*4096;

        // stage S_old
        #pragma unroll
        for (int r=0;r<8;r++) sS[(rg*8+r)*65 + c] = Sreg[r];
        // load G (T^T) linearly
        {
            int i0 = tid*8;
            *(float4*)&sG[i0]   = *(const float4*)&Tg[ofs + i0];
            *(float4*)&sG[i0+4] = *(const float4*)&Tg[ofs + i0 + 4];
        }
        // load Q chunk, build Q^T in shared (stride 68: rows 16B aligned)
        #pragma unroll
        for (int p=0;p<2;p++){
            int idx = tid + p*512;      // 0..1023 = 64 rows x 16 float4
            int t  = idx >> 4;
            int d4 = (idx & 15)*4;
            float4 q = *(const float4*)&Qm[(size_t)(b*TT+t0+t)*DM + colq + d4];
            sQT[(d4+0)*68 + t] = q.x;
            sQT[(d4+1)*68 + t] = q.y;
            sQT[(d4+2)*68 + t] = q.z;
            sQT[(d4+3)*68 + t] = q.w;
        }
        // load M and OI into registers (latency hidden behind matmuls)
        float mac[8], oi[8];
        #pragma unroll
        for (int r=0;r<8;r++){
            mac[r] = Mg[ofs + (size_t)(rg*8+r)*64 + c];
            oi[r]  = OI[(size_t)(b*TT+t0+rg*8+r)*DM + colq + c];
        }
        __syncthreads();

        // O_inter[t][c] = sum_d Q[t][d] S[d][c]  (t = rg*8..+7)
        float oa[8];
        #pragma unroll
        for (int r=0;r<8;r++) oa[r]=0.f;
        for (int d=0; d<DKH; d++){
            float4 q0 = *(const float4*)&sQT[d*68 + rg*8];
            float4 q1 = *(const float4*)&sQT[d*68 + rg*8 + 4];
            float sv = sS[d*65 + c];
            oa[0]+=q0.x*sv; oa[1]+=q0.y*sv; oa[2]+=q0.z*sv; oa[3]+=q0.w*sv;
            oa[4]+=q1.x*sv; oa[5]+=q1.y*sv; oa[6]+=q1.z*sv; oa[7]+=q1.w*sv;
        }
        #pragma unroll
        for (int r=0;r<8;r++) sO[(rg*8+r)*65 + c] = oa[r] + oi[r];

        // S_new[d][c] = sum_d' T[d][d'] S_old[d'][c] + M[d][c]
        float ns[8];
        #pragma unroll
        for (int r=0;r<8;r++) ns[r]=0.f;
        for (int d2=0; d2<DKH; d2++){
            float4 g0 = *(const float4*)&sG[d2*64 + rg*8];
            float4 g1 = *(const float4*)&sG[d2*64 + rg*8 + 4];
            float sv = sS[d2*65 + c];
            ns[0]+=g0.x*sv; ns[1]+=g0.y*sv; ns[2]+=g0.z*sv; ns[3]+=g0.w*sv;
            ns[4]+=g1.x*sv; ns[5]+=g1.y*sv; ns[6]+=g1.z*sv; ns[7]+=g1.w*sv;
        }
        #pragma unroll
        for (int r=0;r<8;r++) Sreg[r] = ns[r] + mac[r];
        __syncthreads();

        // epilogue: RMSNorm * rms_w * gate, write Om
        {
            int tn = tid>>3, ln = tid&7;
            float vv8[8]; float s = 0.f;
            #pragma unroll
            for (int r=0;r<8;r++){
                float v = sO[tn*65 + ln*8 + r];
                vv8[r]=v; s += v*v;
            }
            s += __shfl_xor_sync(0xffffffffu, s, 4, 8);
            s += __shfl_xor_sync(0xffffffffu, s, 2, 8);
            s += __shfl_xor_sync(0xffffffffu, s, 1, 8);
            float scale = rsqrtf(s*(1.0f/DVH) + 1e-6f);
            float gg = GG[(size_t)(b*TT+t0+tn)*HH + h];
            size_t gb = (size_t)(b*TT+t0+tn)*DM + colq + ln*8;
            #pragma unroll
            for (int r=0;r<8;r++)
                Om[gb + r] = vv8[r]*scale*rmsw[h*DVH + ln*8 + r]*gg;
        }
        __syncthreads();   // sO reads done before next chunk re-stages
    }
}

// ---------------------------------------------------------------------------
// Launcher. Inputs in metadata order:
// 0:x 1:wq_conv 2:bq_conv 3:wk_conv 4:bk_conv 5:wv_conv 6:bv_conv
// 7:Wq 8:bq 9:Wk 10:bk 11:Wv 12:bv 13:Wad 14:bad 15:Wau 16:bau
// 17:Wbeta 18:bbeta 19:rms_w 20:Wgd 21:bgd 22:Wgu 23:bgu 24:Wo 25:bo
// ---------------------------------------------------------------------------
extern "C" void kernel_launch(void* const* d_in, const int* in_sizes, int n_in,
                              void* d_out, int out_size)
{
    const float* x     = (const float*)d_in[0];
    const float* wqc   = (const float*)d_in[1];
    const float* bqc   = (const float*)d_in[2];
    const float* wkc   = (const float*)d_in[3];
    const float* bkc   = (const float*)d_in[4];
    const float* wvc   = (const float*)d_in[5];
    const float* bvc   = (const float*)d_in[6];
    const float* Wq    = (const float*)d_in[7];
    const float* bq    = (const float*)d_in[8];
    const float* Wk    = (const float*)d_in[9];
    const float* bk    = (const float*)d_in[10];
    const float* Wv    = (const float*)d_in[11];
    const float* bv    = (const float*)d_in[12];
    const float* Wad   = (const float*)d_in[13];
    const float* bad   = (const float*)d_in[14];
    const float* Wau   = (const float*)d_in[15];
    const float* bau   = (const float*)d_in[16];
    const float* Wbeta = (const float*)d_in[17];
    const float* bbeta = (const float*)d_in[18];
    const float* rms_w = (const float*)d_in[19];
    const float* Wgd   = (const float*)d_in[20];
    const float* bgd   = (const float*)d_in[21];
    const float* Wgu   = (const float*)d_in[22];
    const float* bgu   = (const float*)d_in[23];
    const float* Wo    = (const float*)d_in[24];
    const float* bo    = (const float*)d_in[25];
    float* out = (float*)d_out;

    float* sc = nullptr;
    cudaGetSymbolAddress((void**)&sc, g_scratch);
    const size_t SZ = (size_t)MR*DM;
    float* CQ = sc;          float* CK = sc+SZ;    float* CV = sc+2*SZ;
    float* QB = sc+3*SZ;     float* KB = sc+4*SZ;  float* VB = sc+5*SZ;
    float* AL = sc+6*SZ;     float* OA = sc+7*SZ;
    float* HA = sc+8*SZ;
    float* BE = HA + (size_t)2*MR*RR;
    float* GG = BE + (size_t)MR*HH;
    // after QKV GEMMs the conv buffers are dead -> reuse for T/M/OI
    float* Tg = CQ;   // 1024 x 64 x 64 = MR*DM floats exactly
    float* Mg = CK;
    float* OI = CV;

    // conv + silu pre-activations
    conv_silu_kernel<<<(MR*DM/4)/256, 256>>>(x, wqc,bqc, wkc,bkc, wvc,bvc,
                                             CQ,CK,CV);

    // fused gate branches from raw x
    gates_kernel<<<MR,256>>>(x, Wad,bad, Wgd,bgd, Wbeta,bbeta, Wgu,bgu,
                             HA, BE, GG);

    // big projections: TF32 tensor cores, double-buffered, Q/K/V batched
    const int gemm_smem = 2*2*TBUF*(int)sizeof(unsigned);   // 73728 B
    cudaFuncSetAttribute(gemm_tf32_batch,
                         cudaFuncAttributeMaxDynamicSharedMemorySize, gemm_smem);
    {
        GemmB gq;
        gq.A[0]=CQ;  gq.A[1]=CK;  gq.A[2]=CV;
        gq.W[0]=Wq;  gq.W[1]=Wk;  gq.W[2]=Wv;
        gq.bias[0]=bq; gq.bias[1]=bk; gq.bias[2]=bv;
        gq.C[0]=QB;  gq.C[1]=KB;  gq.C[2]=VB;
        dim3 g3(DM/128, MR/128, 3);
        gemm_tf32_batch<<<g3, 256, gemm_smem>>>(gq, DM, DM);
    }
    // alpha path stays fp32
    dim3 gblk(DM/128, MR/128);
    gemm_tn<1><<<gblk,256>>>(HA, Wau, bau, AL, MR, DM, RR);

    // R1: parallel per-chunk kernel (1024 blocks)
    const int r1_smem = (64*65 + 3*64*64 + 2*64*65 + 64*65 + 2*16*65 + 64 + 64*9)
                        * (int)sizeof(float);   // 126592 B
    cudaFuncSetAttribute(chunk_kernel,
                         cudaFuncAttributeMaxDynamicSharedMemorySize, r1_smem);
    chunk_kernel<<<BHN*NCH, 512, r1_smem>>>(QB, KB, VB, AL, BE, OI, Tg, Mg);

    // R2: sequential combine (32 blocks)
    const int r2_smem = (64*65 + 64*64 + 64*68 + 64*65) * (int)sizeof(float);
    cudaFuncSetAttribute(combine_kernel,
                         cudaFuncAttributeMaxDynamicSharedMemorySize, r2_smem);
    combine_kernel<<<BHN, 512, r2_smem>>>(QB, Tg, Mg, OI, GG, rms_w, OA);

    // output projection (TF32)
    {
        GemmB go;
        go.A[0]=OA;  go.A[1]=OA;  go.A[2]=OA;
        go.W[0]=Wo;  go.W[1]=Wo;  go.W[2]=Wo;
        go.bias[0]=bo; go.bias[1]=bo; go.bias[2]=bo;
        go.C[0]=out; go.C[1]=out; go.C[2]=out;
        dim3 g1(DM/128, MR/128, 1);
        gemm_tf32_batch<<<g1, 256, gemm_smem>>>(go, DM, DM);
    }
}